// round 12
// baseline (speedup 1.0000x reference)
#include <cuda_runtime.h>
#include <cstdint>

#define B      8
#define CH     128
#define OC     3
#define WDIM   512
#define HW     (512 * 512)        // 262144
#define HW4    (HW / 4)           // 65536
#define EPS    1e-8f
#define AFF_SCALE  (0.044194173824159216f)   // 1/sqrt(512)
#define CONV_SCALE (0.08838834764831845f)    // 1/sqrt(128)

#define GRID_X     (HW4 / 256)    // 256
#define GRID_TOTAL (GRID_X * B)   // 2048

// Modulated+demodulated weights, layout [b][o][c]
__device__ float g_w[B * OC * CH];
// Per-batch publish flags + grid-exit counter (reset every launch -> deterministic)
__device__ int g_flag[B];
__device__ int g_done;

// ---------------------------------------------------------------------------
// Fused kernel. grid = (GRID_X, B), block = 256.
// Blocks with linear bid < B (x<8, y==0) are "leaders": each computes the
// modulated+demodulated weights for batch b_lead = blockIdx.x and publishes
// via g_flag[b_lead]. Leaders are the first-dispatched bids -> wave-1
// resident, so waiters can never starve them; a leader publishes its own
// flag BEFORE waiting on flag[0] (published by leader bid 0), so there is
// no circular wait. All blocks then run the DRAM-rate streaming contraction
// (hot loop identical to the measured 160us / 85%-DRAM configuration).
// ---------------------------------------------------------------------------
__global__ void __launch_bounds__(256)
torgb_fused_kernel(const float* __restrict__ x,           // [B, CH, HW]
                   const float* __restrict__ styles,      // [B, WDIM]
                   const float* __restrict__ conv_weight, // [OC, CH]
                   const float* __restrict__ conv_bias,   // [OC]
                   const float* __restrict__ aff_weight,  // [CH, WDIM]
                   const float* __restrict__ aff_bias,    // [CH]
                   float* __restrict__ out)                // [B, OC, HW]
{
    const int b = blockIdx.y;
    const int t = threadIdx.x;

    __shared__ float sw[OC][CH];     // final weights for THIS block's batch
    __shared__ float sbias[OC];

    // ---------------- Leader prologue: compute weights for batch b_lead ----
    if (blockIdx.y == 0 && blockIdx.x < B) {
        const int b_lead = blockIdx.x;
        __shared__ float wraw[OC][CH];
        __shared__ float red[OC][CH];
        __shared__ float dsh[OC];

        const int c  = t >> 1;        // 0..127
        const int hf = t & 1;         // 0..1, 256 elements each

        const float4* st = (const float4*)(styles + (size_t)b_lead * WDIM) + hf * 64;
        const float4* aw = (const float4*)(aff_weight + (size_t)c * WDIM) + hf * 64;
        float acc = 0.f;
#pragma unroll 8
        for (int k = 0; k < 64; ++k) {
            float4 s = st[k];
            float4 a = aw[k];
            acc += s.x * a.x + s.y * a.y + s.z * a.z + s.w * a.w;
        }
        // pair (2c, 2c+1) are adjacent lanes: xor-1 completes the 512-dot
        acc += __shfl_xor_sync(0xffffffffu, acc, 1);

        if (hf == 0) {
            const float z = acc * AFF_SCALE + aff_bias[c];
            const float w0 = conv_weight[0 * CH + c] * z * CONV_SCALE;
            const float w1 = conv_weight[1 * CH + c] * z * CONV_SCALE;
            const float w2 = conv_weight[2 * CH + c] * z * CONV_SCALE;
            wraw[0][c] = w0; red[0][c] = w0 * w0;
            wraw[1][c] = w1; red[1][c] = w1 * w1;
            wraw[2][c] = w2; red[2][c] = w2 * w2;
        }
        __syncthreads();

        // one warp per output channel reduces the 128 squares
        const int wid  = t >> 5;
        const int lane = t & 31;
        if (wid < OC) {
            float s = red[wid][lane] + red[wid][lane + 32] +
                      red[wid][lane + 64] + red[wid][lane + 96];
#pragma unroll
            for (int o = 16; o >= 1; o >>= 1)
                s += __shfl_xor_sync(0xffffffffu, s, o);
            if (lane == 0) dsh[wid] = rsqrtf(s + EPS);
        }
        __syncthreads();

        if (t < CH) {
            g_w[(b_lead * OC + 0) * CH + t] = wraw[0][t] * dsh[0];
            g_w[(b_lead * OC + 1) * CH + t] = wraw[1][t] * dsh[1];
            g_w[(b_lead * OC + 2) * CH + t] = wraw[2][t] * dsh[2];
        }
        __threadfence();               // device-scope: g_w visible before flag
        __syncthreads();
        if (t == 0) atomicExch(&g_flag[b_lead], 1);   // publish
    }

    // ---------------- Wait for this batch's weights, stage to shared -------
    if (t == 0) {
        volatile int* fl = (volatile int*)&g_flag[b];
        while (*fl == 0) __nanosleep(64);
        __threadfence();               // acquire: g_w reads below see stores
    }
    __syncthreads();

    if (t < CH) {
        sw[0][t] = g_w[(b * OC + 0) * CH + t];
        sw[1][t] = g_w[(b * OC + 1) * CH + t];
        sw[2][t] = g_w[(b * OC + 2) * CH + t];
    }
    if (t < OC) sbias[t] = conv_bias[t];
    __syncthreads();

    // ---------------- Hot loop (identical to 160us/85%-DRAM config) --------
    const int idx = blockIdx.x * blockDim.x + t;   // 0..HW4-1

    const float4* xb = (const float4*)(x + (size_t)b * CH * HW);
    float4*       ob = (float4*)(out + (size_t)b * OC * HW);

    float4 a0 = make_float4(0.f, 0.f, 0.f, 0.f), b0v = a0;
    float4 a1 = a0, b1v = a0;
    float4 a2 = a0, b2v = a0;

#pragma unroll 4
    for (int c = 0; c < CH; c += 2) {
        const float4 xv0 = __ldcs(&xb[(size_t)c * HW4 + idx]);
        const float4 xv1 = __ldcs(&xb[(size_t)(c + 1) * HW4 + idx]);
        {
            const float w0 = sw[0][c], w1 = sw[1][c], w2 = sw[2][c];
            a0.x = fmaf(w0, xv0.x, a0.x); a0.y = fmaf(w0, xv0.y, a0.y);
            a0.z = fmaf(w0, xv0.z, a0.z); a0.w = fmaf(w0, xv0.w, a0.w);
            a1.x = fmaf(w1, xv0.x, a1.x); a1.y = fmaf(w1, xv0.y, a1.y);
            a1.z = fmaf(w1, xv0.z, a1.z); a1.w = fmaf(w1, xv0.w, a1.w);
            a2.x = fmaf(w2, xv0.x, a2.x); a2.y = fmaf(w2, xv0.y, a2.y);
            a2.z = fmaf(w2, xv0.z, a2.z); a2.w = fmaf(w2, xv0.w, a2.w);
        }
        {
            const float w0 = sw[0][c + 1], w1 = sw[1][c + 1], w2 = sw[2][c + 1];
            b0v.x = fmaf(w0, xv1.x, b0v.x); b0v.y = fmaf(w0, xv1.y, b0v.y);
            b0v.z = fmaf(w0, xv1.z, b0v.z); b0v.w = fmaf(w0, xv1.w, b0v.w);
            b1v.x = fmaf(w1, xv1.x, b1v.x); b1v.y = fmaf(w1, xv1.y, b1v.y);
            b1v.z = fmaf(w1, xv1.z, b1v.z); b1v.w = fmaf(w1, xv1.w, b1v.w);
            b2v.x = fmaf(w2, xv1.x, b2v.x); b2v.y = fmaf(w2, xv1.y, b2v.y);
            b2v.z = fmaf(w2, xv1.z, b2v.z); b2v.w = fmaf(w2, xv1.w, b2v.w);
        }
    }

    const float c0 = sbias[0], c1 = sbias[1], c2 = sbias[2];
    a0.x += b0v.x + c0; a0.y += b0v.y + c0; a0.z += b0v.z + c0; a0.w += b0v.w + c0;
    a1.x += b1v.x + c1; a1.y += b1v.y + c1; a1.z += b1v.z + c1; a1.w += b1v.w + c1;
    a2.x += b2v.x + c2; a2.y += b2v.y + c2; a2.z += b2v.z + c2; a2.w += b2v.w + c2;

    ob[(size_t)0 * HW4 + idx] = a0;
    ob[(size_t)1 * HW4 + idx] = a1;
    ob[(size_t)2 * HW4 + idx] = a2;

    // ---------------- Grid-exit cleanup: reset flags for the next launch ---
    // Every thread-0 arrives here only AFTER its block passed the flag wait,
    // so the last arriver can safely reset. Makes every launch identical work.
    if (t == 0) {
        const int d = atomicAdd(&g_done, 1);
        if (d == GRID_TOTAL - 1) {
#pragma unroll
            for (int i = 0; i < B; ++i) atomicExch(&g_flag[i], 0);
            atomicExch(&g_done, 0);
        }
    }
}

// ---------------------------------------------------------------------------
// Inputs (metadata order): x, styles, conv_weight, conv_bias, aff_weight, aff_bias
// ---------------------------------------------------------------------------
extern "C" void kernel_launch(void* const* d_in, const int* in_sizes, int n_in,
                              void* d_out, int out_size)
{
    const float* x           = (const float*)d_in[0];
    const float* styles      = (const float*)d_in[1];
    const float* conv_weight = (const float*)d_in[2];
    const float* conv_bias   = (const float*)d_in[3];
    const float* aff_weight  = (const float*)d_in[4];
    const float* aff_bias    = (const float*)d_in[5];
    float* out = (float*)d_out;

    dim3 grid(GRID_X, B);
    torgb_fused_kernel<<<grid, 256>>>(x, styles, conv_weight, conv_bias,
                                      aff_weight, aff_bias, out);
}

// round 13
// speedup vs baseline: 1.3577x; 1.3577x over previous
#include <cuda_runtime.h>
#include <cstdint>

#define B      8
#define CH     128
#define OC     3
#define WDIM   512
#define HW     (512 * 512)        // 262144
#define HW4    (HW / 4)           // 65536
#define EPS    1e-8f
#define AFF_SCALE  (0.044194173824159216f)   // 1/sqrt(512)
#define CONV_SCALE (0.08838834764831845f)    // 1/sqrt(128)

// Modulated+demodulated weights, layout [b][o][c]
__device__ float g_w[B * OC * CH];

// ---------------------------------------------------------------------------
// Kernel 1: compute per-sample modulated + demodulated weights (3072 floats)
// grid = (B), block = (CH)   [exact R4 configuration — measured 174.6us total]
// ---------------------------------------------------------------------------
__global__ void compute_w_kernel(const float* __restrict__ styles,      // [B, WDIM]
                                 const float* __restrict__ conv_weight, // [OC, CH]
                                 const float* __restrict__ aff_weight,  // [CH, WDIM]
                                 const float* __restrict__ aff_bias)    // [CH]
{
    const int b = blockIdx.x;
    const int c = threadIdx.x;   // 0..127

    // z[b][c] = dot(styles[b,:], aff_weight[c,:]) * AFF_SCALE + aff_bias[c]
    const float4* st = (const float4*)(styles + (size_t)b * WDIM);
    const float4* aw = (const float4*)(aff_weight + (size_t)c * WDIM);
    float acc = 0.f;
#pragma unroll 8
    for (int k = 0; k < WDIM / 4; ++k) {
        float4 s = st[k];
        float4 a = aw[k];
        acc += s.x * a.x + s.y * a.y + s.z * a.z + s.w * a.w;
    }
    const float z = acc * AFF_SCALE + aff_bias[c];

    float w0 = conv_weight[0 * CH + c] * z * CONV_SCALE;
    float w1 = conv_weight[1 * CH + c] * z * CONV_SCALE;
    float w2 = conv_weight[2 * CH + c] * z * CONV_SCALE;

    // Block reduction of sum-of-squares per output channel
    __shared__ float red[OC][CH];
    red[0][c] = w0 * w0;
    red[1][c] = w1 * w1;
    red[2][c] = w2 * w2;
    __syncthreads();
    for (int s = CH / 2; s > 0; s >>= 1) {
        if (c < s) {
            red[0][c] += red[0][c + s];
            red[1][c] += red[1][c + s];
            red[2][c] += red[2][c + s];
        }
        __syncthreads();
    }
    const float d0 = rsqrtf(red[0][0] + EPS);
    const float d1 = rsqrtf(red[1][0] + EPS);
    const float d2 = rsqrtf(red[2][0] + EPS);

    g_w[(b * OC + 0) * CH + c] = w0 * d0;
    g_w[(b * OC + 1) * CH + c] = w1 * d1;
    g_w[(b * OC + 2) * CH + c] = w2 * d2;
}

// ---------------------------------------------------------------------------
// Kernel 2: streaming batched per-sample 1x1 conv (channel contraction)
// out[b,o,hw] = sum_c w[b,o,c] * x[b,c,hw] + bias[o]
// grid = (HW4/256, B), block = 256, one float4 pixel-group per thread
// (byte-identical to the measured 160.5us / 85%-DRAM configuration)
// ---------------------------------------------------------------------------
__global__ void __launch_bounds__(256)
torgb_main_kernel(const float* __restrict__ x,         // [B, CH, HW]
                  const float* __restrict__ conv_bias, // [OC]
                  float* __restrict__ out)             // [B, OC, HW]
{
    const int b = blockIdx.y;
    const int t = threadIdx.x;

    __shared__ float sw[OC][CH];
    __shared__ float sbias[OC];
    if (t < CH) {
        sw[0][t] = g_w[(b * OC + 0) * CH + t];
        sw[1][t] = g_w[(b * OC + 1) * CH + t];
        sw[2][t] = g_w[(b * OC + 2) * CH + t];
    }
    if (t < OC) sbias[t] = conv_bias[t];
    __syncthreads();

    const int idx = blockIdx.x * blockDim.x + t;   // 0..HW4-1

    const float4* xb = (const float4*)(x + (size_t)b * CH * HW);
    float4*       ob = (float4*)(out + (size_t)b * OC * HW);

    // Two independent accumulator sets (even/odd channels) to shorten FFMA
    // dependency chains and let ptxas batch more LDGs in flight.
    float4 a0 = make_float4(0.f, 0.f, 0.f, 0.f), b0v = a0;
    float4 a1 = a0, b1v = a0;
    float4 a2 = a0, b2v = a0;

#pragma unroll 4
    for (int c = 0; c < CH; c += 2) {
        const float4 xv0 = __ldcs(&xb[(size_t)c * HW4 + idx]);
        const float4 xv1 = __ldcs(&xb[(size_t)(c + 1) * HW4 + idx]);
        {
            const float w0 = sw[0][c], w1 = sw[1][c], w2 = sw[2][c];
            a0.x = fmaf(w0, xv0.x, a0.x); a0.y = fmaf(w0, xv0.y, a0.y);
            a0.z = fmaf(w0, xv0.z, a0.z); a0.w = fmaf(w0, xv0.w, a0.w);
            a1.x = fmaf(w1, xv0.x, a1.x); a1.y = fmaf(w1, xv0.y, a1.y);
            a1.z = fmaf(w1, xv0.z, a1.z); a1.w = fmaf(w1, xv0.w, a1.w);
            a2.x = fmaf(w2, xv0.x, a2.x); a2.y = fmaf(w2, xv0.y, a2.y);
            a2.z = fmaf(w2, xv0.z, a2.z); a2.w = fmaf(w2, xv0.w, a2.w);
        }
        {
            const float w0 = sw[0][c + 1], w1 = sw[1][c + 1], w2 = sw[2][c + 1];
            b0v.x = fmaf(w0, xv1.x, b0v.x); b0v.y = fmaf(w0, xv1.y, b0v.y);
            b0v.z = fmaf(w0, xv1.z, b0v.z); b0v.w = fmaf(w0, xv1.w, b0v.w);
            b1v.x = fmaf(w1, xv1.x, b1v.x); b1v.y = fmaf(w1, xv1.y, b1v.y);
            b1v.z = fmaf(w1, xv1.z, b1v.z); b1v.w = fmaf(w1, xv1.w, b1v.w);
            b2v.x = fmaf(w2, xv1.x, b2v.x); b2v.y = fmaf(w2, xv1.y, b2v.y);
            b2v.z = fmaf(w2, xv1.z, b2v.z); b2v.w = fmaf(w2, xv1.w, b2v.w);
        }
    }

    const float c0 = sbias[0], c1 = sbias[1], c2 = sbias[2];
    a0.x += b0v.x + c0; a0.y += b0v.y + c0; a0.z += b0v.z + c0; a0.w += b0v.w + c0;
    a1.x += b1v.x + c1; a1.y += b1v.y + c1; a1.z += b1v.z + c1; a1.w += b1v.w + c1;
    a2.x += b2v.x + c2; a2.y += b2v.y + c2; a2.z += b2v.z + c2; a2.w += b2v.w + c2;

    ob[(size_t)0 * HW4 + idx] = a0;
    ob[(size_t)1 * HW4 + idx] = a1;
    ob[(size_t)2 * HW4 + idx] = a2;
}

// ---------------------------------------------------------------------------
// Inputs (metadata order): x, styles, conv_weight, conv_bias, aff_weight, aff_bias
// ---------------------------------------------------------------------------
extern "C" void kernel_launch(void* const* d_in, const int* in_sizes, int n_in,
                              void* d_out, int out_size)
{
    const float* x           = (const float*)d_in[0];
    const float* styles      = (const float*)d_in[1];
    const float* conv_weight = (const float*)d_in[2];
    const float* conv_bias   = (const float*)d_in[3];
    const float* aff_weight  = (const float*)d_in[4];
    const float* aff_bias    = (const float*)d_in[5];
    float* out = (float*)d_out;

    compute_w_kernel<<<B, CH>>>(styles, conv_weight, aff_weight, aff_bias);

    dim3 grid(HW4 / 256, B);
    torgb_main_kernel<<<grid, 256>>>(x, conv_bias, out);
}